// round 1
// baseline (speedup 1.0000x reference)
#include <cuda_runtime.h>
#include <mma.h>
#include <cstdint>

using namespace nvcuda;

#define SEQ 2048
#define EMB 2048
#define NB  2
#define NH  16
#define DH  128
#define MTOT (NB*SEQ)   // 4096 rows for all projections

// ---------------- scratch (static device globals; no runtime allocation) ----
__device__ float g_q  [MTOT*EMB];
__device__ float g_k  [MTOT*EMB];
__device__ float g_v  [MTOT*EMB];
__device__ float g_vp [NB*NH*SEQ*DH];
__device__ float g_sc [134217728];   // 2*16*2048*2048 scores (512 MB)
__device__ float g_ctx[MTOT*EMB];
__device__ float g_xa [MTOT*EMB];
__device__ float g_h  [MTOT*EMB];
__device__ float g_w  [MTOT*EMB];
__device__ float g_u  [MTOT*EMB];

// ---------------- block reductions ----------------
__device__ __forceinline__ float blk_sum(float v) {
    __shared__ float sh_s[32];
    __shared__ float tot_s;
    int lane = threadIdx.x & 31, w = threadIdx.x >> 5;
    #pragma unroll
    for (int o = 16; o; o >>= 1) v += __shfl_xor_sync(0xffffffffu, v, o);
    if (lane == 0) sh_s[w] = v;
    __syncthreads();
    if (threadIdx.x == 0) {
        float r = 0.f;
        int nw = blockDim.x >> 5;
        for (int i = 0; i < nw; i++) r += sh_s[i];
        tot_s = r;
    }
    __syncthreads();
    float r = tot_s;
    __syncthreads();   // protect shared for subsequent calls
    return r;
}

__device__ __forceinline__ float blk_max(float v) {
    __shared__ float sh_m[32];
    __shared__ float tot_m;
    int lane = threadIdx.x & 31, w = threadIdx.x >> 5;
    #pragma unroll
    for (int o = 16; o; o >>= 1) v = fmaxf(v, __shfl_xor_sync(0xffffffffu, v, o));
    if (lane == 0) sh_m[w] = v;
    __syncthreads();
    if (threadIdx.x == 0) {
        float r = -3.4e38f;
        int nw = blockDim.x >> 5;
        for (int i = 0; i < nw; i++) r = fmaxf(r, sh_m[i]);
        tot_m = r;
    }
    __syncthreads();
    float r = tot_m;
    __syncthreads();
    return r;
}

// ---------------- TF32 wmma GEMMs ----------------
// Tile: 128x128, BK=16, 256 threads (8 warps, 4x2), warp tile 32x64.
constexpr int BM = 128, BN = 128, BK = 16;

// C[M,N] = alpha * A[M,K] @ B[N,K]^T  (+ Res), row-major, batched via blockIdx.z
// per-z offset = (z/zdiv)*s1 + (z%zdiv)*s2 for each of A,B,C(,Res uses C offsets)
template<bool RES, bool CSKIP>
__global__ void __launch_bounds__(256)
gemm_nt(int K,
        const float* __restrict__ A, int lda,
        const float* __restrict__ B, int ldb,
        float* __restrict__ C, int ldc,
        const float* __restrict__ R,
        float alpha, int zdiv,
        long long sA1, long long sA2,
        long long sB1, long long sB2,
        long long sC1, long long sC2)
{
    const int bn0 = blockIdx.x * BN;
    const int bm0 = blockIdx.y * BM;
    if (CSKIP && bn0 > bm0 + BM - 1) return;   // fully above causal diagonal
    const int z = blockIdx.z;
    const long long offA = (long long)(z / zdiv) * sA1 + (long long)(z % zdiv) * sA2;
    const long long offB = (long long)(z / zdiv) * sB1 + (long long)(z % zdiv) * sB2;
    const long long offC = (long long)(z / zdiv) * sC1 + (long long)(z % zdiv) * sC2;
    A += offA; B += offB; C += offC;

    __shared__ float As[BM][BK + 4];
    __shared__ float Bs[BN][BK + 4];

    const int tid = threadIdx.x;
    const int wid = tid >> 5;
    const int wm = (wid & 3) * 32;
    const int wn = (wid >> 2) * 64;

    wmma::fragment<wmma::accumulator, 16, 16, 8, float> acc[2][4];
    #pragma unroll
    for (int mi = 0; mi < 2; mi++)
        #pragma unroll
        for (int ni = 0; ni < 4; ni++) {
            if (RES)
                wmma::load_matrix_sync(acc[mi][ni],
                    R + offC + (long long)(bm0 + wm + mi * 16) * ldc + (bn0 + wn + ni * 16),
                    ldc, wmma::mem_row_major);
            else
                wmma::fill_fragment(acc[mi][ni], 0.0f);
        }

    const int lrow = tid >> 2;
    const int lq4  = (tid & 3) * 4;

    for (int k0 = 0; k0 < K; k0 += BK) {
        #pragma unroll
        for (int rp = 0; rp < 2; rp++) {
            const int rr = lrow + rp * 64;
            float4 av = *reinterpret_cast<const float4*>(A + (long long)(bm0 + rr) * lda + k0 + lq4);
            float4 bv = *reinterpret_cast<const float4*>(B + (long long)(bn0 + rr) * ldb + k0 + lq4);
            As[rr][lq4 + 0] = wmma::__float_to_tf32(av.x);
            As[rr][lq4 + 1] = wmma::__float_to_tf32(av.y);
            As[rr][lq4 + 2] = wmma::__float_to_tf32(av.z);
            As[rr][lq4 + 3] = wmma::__float_to_tf32(av.w);
            Bs[rr][lq4 + 0] = wmma::__float_to_tf32(bv.x);
            Bs[rr][lq4 + 1] = wmma::__float_to_tf32(bv.y);
            Bs[rr][lq4 + 2] = wmma::__float_to_tf32(bv.z);
            Bs[rr][lq4 + 3] = wmma::__float_to_tf32(bv.w);
        }
        __syncthreads();
        #pragma unroll
        for (int kk = 0; kk < BK; kk += 8) {
            wmma::fragment<wmma::matrix_a, 16, 16, 8, wmma::precision::tf32, wmma::row_major> af[2];
            wmma::fragment<wmma::matrix_b, 16, 16, 8, wmma::precision::tf32, wmma::col_major> bf[4];
            #pragma unroll
            for (int mi = 0; mi < 2; mi++)
                wmma::load_matrix_sync(af[mi], &As[wm + mi * 16][kk], BK + 4);
            #pragma unroll
            for (int ni = 0; ni < 4; ni++)
                wmma::load_matrix_sync(bf[ni], &Bs[wn + ni * 16][kk], BK + 4);
            #pragma unroll
            for (int mi = 0; mi < 2; mi++)
                #pragma unroll
                for (int ni = 0; ni < 4; ni++)
                    wmma::mma_sync(acc[mi][ni], af[mi], bf[ni], acc[mi][ni]);
        }
        __syncthreads();
    }

    #pragma unroll
    for (int mi = 0; mi < 2; mi++)
        #pragma unroll
        for (int ni = 0; ni < 4; ni++) {
            if (alpha != 1.0f) {
                #pragma unroll
                for (int e = 0; e < acc[mi][ni].num_elements; e++) acc[mi][ni].x[e] *= alpha;
            }
            wmma::store_matrix_sync(C + (long long)(bm0 + wm + mi * 16) * ldc + (bn0 + wn + ni * 16),
                                    acc[mi][ni], ldc, wmma::mem_row_major);
        }
}

// C[M,N] = A[M,K] @ B[K,N], row-major; optional causal k-cap (K limited to bm0+BM)
template<bool KCAP>
__global__ void __launch_bounds__(256)
gemm_nn(int K,
        const float* __restrict__ A, int lda,
        const float* __restrict__ B, int ldb,
        float* __restrict__ C, int ldc,
        int zdiv,
        long long sA1, long long sA2,
        long long sB1, long long sB2,
        long long sC1, long long sC2)
{
    const int bn0 = blockIdx.x * BN;
    const int bm0 = blockIdx.y * BM;
    const int z = blockIdx.z;
    const long long offA = (long long)(z / zdiv) * sA1 + (long long)(z % zdiv) * sA2;
    const long long offB = (long long)(z / zdiv) * sB1 + (long long)(z % zdiv) * sB2;
    const long long offC = (long long)(z / zdiv) * sC1 + (long long)(z % zdiv) * sC2;
    A += offA; B += offB; C += offC;

    __shared__ float As[BM][BK + 4];
    __shared__ float Bs[BK][BN + 4];

    const int tid = threadIdx.x;
    const int wid = tid >> 5;
    const int wm = (wid & 3) * 32;
    const int wn = (wid >> 2) * 64;

    wmma::fragment<wmma::accumulator, 16, 16, 8, float> acc[2][4];
    #pragma unroll
    for (int mi = 0; mi < 2; mi++)
        #pragma unroll
        for (int ni = 0; ni < 4; ni++)
            wmma::fill_fragment(acc[mi][ni], 0.0f);

    const int lrow = tid >> 2;
    const int lq4  = (tid & 3) * 4;
    const int brow = tid >> 5;            // 0..7
    const int bq4  = (tid & 31) * 4;      // 0..124

    const int kend = KCAP ? min(K, bm0 + BM) : K;

    for (int k0 = 0; k0 < kend; k0 += BK) {
        #pragma unroll
        for (int rp = 0; rp < 2; rp++) {
            const int rr = lrow + rp * 64;
            float4 av = *reinterpret_cast<const float4*>(A + (long long)(bm0 + rr) * lda + k0 + lq4);
            As[rr][lq4 + 0] = wmma::__float_to_tf32(av.x);
            As[rr][lq4 + 1] = wmma::__float_to_tf32(av.y);
            As[rr][lq4 + 2] = wmma::__float_to_tf32(av.z);
            As[rr][lq4 + 3] = wmma::__float_to_tf32(av.w);
            const int kr = brow + rp * 8;
            float4 bv = *reinterpret_cast<const float4*>(B + (long long)(k0 + kr) * ldb + bn0 + bq4);
            Bs[kr][bq4 + 0] = wmma::__float_to_tf32(bv.x);
            Bs[kr][bq4 + 1] = wmma::__float_to_tf32(bv.y);
            Bs[kr][bq4 + 2] = wmma::__float_to_tf32(bv.z);
            Bs[kr][bq4 + 3] = wmma::__float_to_tf32(bv.w);
        }
        __syncthreads();
        #pragma unroll
        for (int kk = 0; kk < BK; kk += 8) {
            wmma::fragment<wmma::matrix_a, 16, 16, 8, wmma::precision::tf32, wmma::row_major> af[2];
            wmma::fragment<wmma::matrix_b, 16, 16, 8, wmma::precision::tf32, wmma::row_major> bf[4];
            #pragma unroll
            for (int mi = 0; mi < 2; mi++)
                wmma::load_matrix_sync(af[mi], &As[wm + mi * 16][kk], BK + 4);
            #pragma unroll
            for (int ni = 0; ni < 4; ni++)
                wmma::load_matrix_sync(bf[ni], &Bs[kk][wn + ni * 16], BN + 4);
            #pragma unroll
            for (int mi = 0; mi < 2; mi++)
                #pragma unroll
                for (int ni = 0; ni < 4; ni++)
                    wmma::mma_sync(acc[mi][ni], af[mi], bf[ni], acc[mi][ni]);
        }
        __syncthreads();
    }

    #pragma unroll
    for (int mi = 0; mi < 2; mi++)
        #pragma unroll
        for (int ni = 0; ni < 4; ni++)
            wmma::store_matrix_sync(C + (long long)(bm0 + wm + mi * 16) * ldc + (bn0 + wn + ni * 16),
                                    acc[mi][ni], ldc, wmma::mem_row_major);
}

// ---------------- attention helpers ----------------
// vh[b,s,d,h] = v[b,s, d*H+h]  ->  Vp[(b*H+h), s, d] contiguous
__global__ void repack_v_k(const float* __restrict__ v, float* __restrict__ vp) {
    const int total = NB * NH * SEQ * DH;   // 2^23
    for (int idx = blockIdx.x * blockDim.x + threadIdx.x; idx < total;
         idx += gridDim.x * blockDim.x) {
        int d = idx & 127;
        int s = (idx >> 7) & 2047;
        int h = (idx >> 18) & 15;
        int b = idx >> 22;
        vp[idx] = v[((size_t)(b * SEQ + s)) * EMB + d * NH + h];
    }
}

__global__ void softmax_causal_k(float* __restrict__ sc) {
    const int t  = blockIdx.x;
    const int bh = blockIdx.y;
    float* row = sc + ((size_t)bh * SEQ + t) * SEQ;
    __shared__ float buf[SEQ];
    const int n = t + 1;
    float mx = -3.4e38f;
    for (int i = threadIdx.x; i < n; i += blockDim.x) {
        float v = row[i]; buf[i] = v; mx = fmaxf(mx, v);
    }
    mx = blk_max(mx);
    float sum = 0.f;
    for (int i = threadIdx.x; i < n; i += blockDim.x) {
        float e = __expf(buf[i] - mx); buf[i] = e; sum += e;
    }
    sum = blk_sum(sum);
    const float inv = 1.0f / sum;
    for (int i = threadIdx.x; i < n; i += blockDim.x) row[i] = buf[i] * inv;
    for (int i = n + threadIdx.x; i < SEQ; i += blockDim.x) row[i] = 0.0f;
}

// ---------------- norms / elementwise ----------------
__global__ void layernorm_k(float* __restrict__ x, const float* __restrict__ g,
                            const float* __restrict__ b) {
    float* row = x + (size_t)blockIdx.x * EMB;
    __shared__ float buf[EMB];
    float s = 0.f;
    for (int i = threadIdx.x; i < EMB; i += blockDim.x) { float v = row[i]; buf[i] = v; s += v; }
    const float mu = blk_sum(s) * (1.0f / EMB);
    float sq = 0.f;
    for (int i = threadIdx.x; i < EMB; i += blockDim.x) { float d = buf[i] - mu; sq += d * d; }
    const float var = blk_sum(sq) * (1.0f / EMB);
    const float inv = rsqrtf(var + 1e-5f);
    for (int i = threadIdx.x; i < EMB; i += blockDim.x)
        row[i] = (buf[i] - mu) * inv * g[i] + b[i];
}

__global__ void rmsnorm_k(float* __restrict__ x, const float* __restrict__ g) {
    float* row = x + (size_t)blockIdx.x * EMB;
    __shared__ float buf[EMB];
    float ss = 0.f;
    for (int i = threadIdx.x; i < EMB; i += blockDim.x) { float v = row[i]; buf[i] = v; ss += v * v; }
    ss = blk_sum(ss);
    const float sc = rsqrtf(ss * (1.0f / EMB) + 1e-6f);
    for (int i = threadIdx.x; i < EMB; i += blockDim.x) row[i] = g[i] * buf[i] * sc;
}

__global__ void swiglu_k(float* __restrict__ w, const float* __restrict__ u,
                         const float* __restrict__ beta) {
    const float b = beta[0];
    const int total = MTOT * EMB;
    for (int i = blockIdx.x * blockDim.x + threadIdx.x; i < total;
         i += gridDim.x * blockDim.x) {
        float wv = w[i];
        float s = 1.0f / (1.0f + __expf(-b * wv));
        w[i] = wv * s * u[i];
    }
}

// out = x2 + mlp_rms_g * g * rsqrt(mean(g^2)+eps)
__global__ void final_k(const float* __restrict__ x2, const float* __restrict__ gg,
                        const float* __restrict__ gamma, float* __restrict__ out) {
    const size_t r = blockIdx.x;
    const float* grow = gg + r * EMB;
    __shared__ float buf[EMB];
    float ss = 0.f;
    for (int i = threadIdx.x; i < EMB; i += blockDim.x) { float v = grow[i]; buf[i] = v; ss += v * v; }
    ss = blk_sum(ss);
    const float sc = rsqrtf(ss * (1.0f / EMB) + 1e-6f);
    for (int i = threadIdx.x; i < EMB; i += blockDim.x)
        out[r * EMB + i] = x2[r * EMB + i] + gamma[i] * buf[i] * sc;
}

// ---------------- launcher ----------------
extern "C" void kernel_launch(void* const* d_in, const int* in_sizes, int n_in,
                              void* d_out, int out_size) {
    const float* x     = (const float*)d_in[0];
    const float* Wq    = (const float*)d_in[1];
    const float* Wk    = (const float*)d_in[2];
    const float* Wv    = (const float*)d_in[3];
    const float* Wo    = (const float*)d_in[4];
    const float* ln_g  = (const float*)d_in[5];
    const float* ln_b  = (const float*)d_in[6];
    const float* rms_g = (const float*)d_in[7];
    const float* W0    = (const float*)d_in[8];
    const float* swW   = (const float*)d_in[9];
    const float* swV   = (const float*)d_in[10];
    const float* swb   = (const float*)d_in[11];
    const float* mrg   = (const float*)d_in[12];
    float* out = (float*)d_out;

    float *q, *k, *v, *vp, *sc, *ctx, *xa, *h, *w, *u;
    cudaGetSymbolAddress((void**)&q,   g_q);
    cudaGetSymbolAddress((void**)&k,   g_k);
    cudaGetSymbolAddress((void**)&v,   g_v);
    cudaGetSymbolAddress((void**)&vp,  g_vp);
    cudaGetSymbolAddress((void**)&sc,  g_sc);
    cudaGetSymbolAddress((void**)&ctx, g_ctx);
    cudaGetSymbolAddress((void**)&xa,  g_xa);
    cudaGetSymbolAddress((void**)&h,   g_h);
    cudaGetSymbolAddress((void**)&w,   g_w);
    cudaGetSymbolAddress((void**)&u,   g_u);

    const float scale = 0.08838834764831845f;  // 1/sqrt(128)
    dim3 blk(256);
    dim3 gp(EMB / BN, MTOT / BM, 1);           // (16,32,1) projections

    // q, k(*scale), v projections: NT GEMM vs x
    gemm_nt<false, false><<<gp, blk>>>(EMB, x, EMB, Wq, EMB, q, EMB, nullptr, 1.0f, 1, 0,0,0,0,0,0);
    gemm_nt<false, false><<<gp, blk>>>(EMB, x, EMB, Wk, EMB, k, EMB, nullptr, scale, 1, 0,0,0,0,0,0);
    gemm_nt<false, false><<<gp, blk>>>(EMB, x, EMB, Wv, EMB, v, EMB, nullptr, 1.0f, 1, 0,0,0,0,0,0);

    repack_v_k<<<4096, 256>>>(v, vp);

    // scores[b,h,t,s] = Q_h @ K_h^T (batched, skip blocks above diagonal)
    dim3 gs(SEQ / BN, SEQ / BM, NB * NH);      // (16,16,32)
    gemm_nt<false, true><<<gs, blk>>>(DH,
        q, EMB, k, EMB, sc, SEQ, nullptr, 1.0f, NH,
        (long long)SEQ * EMB, (long long)DH,
        (long long)SEQ * EMB, (long long)DH,
        (long long)NH * SEQ * SEQ, (long long)SEQ * SEQ);

    softmax_causal_k<<<dim3(SEQ, NB * NH), 256>>>(sc);

    // ctx[b,t,h*Dh+d] = P @ Vp (causal k-cap), written directly into packed layout
    dim3 gpv(DH / BN, SEQ / BM, NB * NH);      // (1,16,32)
    gemm_nn<true><<<gpv, blk>>>(SEQ,
        sc, SEQ, vp, DH, ctx, EMB, NH,
        (long long)NH * SEQ * SEQ, (long long)SEQ * SEQ,
        (long long)NH * SEQ * DH,  (long long)SEQ * DH,
        (long long)SEQ * EMB,      (long long)DH);

    layernorm_k<<<MTOT, 256>>>(ctx, ln_g, ln_b);

    // xa = x + ctx @ Wo^T  (residual folded into accumulator init)
    gemm_nt<true, false><<<gp, blk>>>(EMB, ctx, EMB, Wo, EMB, xa, EMB, x, 1.0f, 1, 0,0,0,0,0,0);

    rmsnorm_k<<<MTOT, 256>>>(xa, rms_g);       // xa becomes x2 (MLP residual base)

    gemm_nt<false, false><<<gp, blk>>>(EMB, xa, EMB, W0,  EMB, h, EMB, nullptr, 1.0f, 1, 0,0,0,0,0,0);
    gemm_nt<false, false><<<gp, blk>>>(EMB, h,  EMB, swW, EMB, w, EMB, nullptr, 1.0f, 1, 0,0,0,0,0,0);
    gemm_nt<false, false><<<gp, blk>>>(EMB, h,  EMB, swV, EMB, u, EMB, nullptr, 1.0f, 1, 0,0,0,0,0,0);

    swiglu_k<<<4096, 256>>>(w, u, swb);        // w = swish(w)*u

    final_k<<<MTOT, 256>>>(xa, w, mrg, out);   // out = x2 + rmsnorm(g)
}

// round 3
// speedup vs baseline: 3.1027x; 3.1027x over previous
#include <cuda_runtime.h>
#include <cuda_fp16.h>
#include <mma.h>
#include <cstdint>

using namespace nvcuda;

#define SEQ 2048
#define EMB 2048
#define NB  2
#define NH  16
#define DH  128
#define MTOT (NB*SEQ)   // 4096

// ---------------- scratch (static device globals) ----------------
__device__ __half g_xh [MTOT*EMB];
__device__ __half g_wh [7][EMB*EMB];
__device__ __half g_qh [MTOT*EMB];       // [bh, t, d]
__device__ __half g_kh [MTOT*EMB];       // [bh, s, d] (scaled)
__device__ __half g_v  [MTOT*EMB];       // [b, s, E]
__device__ __half g_vp [MTOT*EMB];       // [bh, d, s]
__device__ float  g_sc [NB*NH*SEQ*SEQ];  // scores fp32 (512MB)
__device__ __half g_pr [NB*NH*SEQ*SEQ];  // probs half (256MB)
__device__ float  g_ctx[MTOT*EMB];
__device__ __half g_cth[MTOT*EMB];
__device__ float  g_xa [MTOT*EMB];
__device__ __half g_x2h[MTOT*EMB];
__device__ __half g_hh [MTOT*EMB];
__device__ float  g_w  [MTOT*EMB];
__device__ float  g_u  [MTOT*EMB];

__device__ __forceinline__ uint32_t smem_u32(const void* p) {
    uint32_t a;
    asm("{ .reg .u64 t; cvta.to.shared.u64 t, %1; cvt.u32.u64 %0, t; }" : "=r"(a) : "l"(p));
    return a;
}

// ---------------- fp16 wmma NT GEMM, cp.async double-buffered ----------------
// C[128,128] tile = A[128,K] @ B[128,K]^T ; K in chunks of 32 halves.
constexpr int BM = 128, BN = 128, PITCH = 40;           // pitch in halves
constexpr int STG_BYTES   = BM * PITCH * 2;             // 10240 per operand
constexpr int STAGE_BYTES = 2 * STG_BYTES;              // 20480 (A+B)
constexpr int SMEM_GEMM   = 2 * STAGE_BYTES + 8 * 1024; // 49152

template<bool HOUT, bool HSPLIT, bool RES, bool CSKIP, bool KCAP>
__global__ void __launch_bounds__(256)
gemm_h(int nk,
       const __half* __restrict__ A, int lda, int zRowA,
       const __half* __restrict__ B, int ldb, int zRowB,
       float* __restrict__ C, __half* __restrict__ Ch, int ldc,
       const float* __restrict__ Rres, float alpha, int zdiv,
       long long sC1, long long sC2)
{
    const int bn0 = blockIdx.x * BN;
    const int bm0 = blockIdx.y * BM;
    if (CSKIP && bn0 > bm0 + BM - 1) return;     // fully above causal diagonal
    const int z = blockIdx.z;
    if (KCAP) nk = min(nk, (bm0 >> 5) + 4);      // causal k-cap (32-elem chunks)

    extern __shared__ __align__(128) char smem[];
    const int tid  = threadIdx.x;
    const int wid  = tid >> 5;
    const int lane = tid & 31;
    const int wm = (wid & 3) * 32;
    const int wn = (wid >> 2) * 64;

    const __half* Abase = A + (size_t)(z * zRowA + bm0) * lda;
    const __half* Bbase = B + (size_t)(z * zRowB + bn0) * ldb;
    const long long coff = (long long)(z / zdiv) * sC1 + (long long)(z % zdiv) * sC2;

    auto load_chunk = [&](int kc) {
        const int st = kc & 1;
        char* sA = smem + st * STAGE_BYTES;
        char* sB = sA + STG_BYTES;
        const __half* ag = Abase + kc * 32;
        const __half* bg = Bbase + kc * 32;
        #pragma unroll
        for (int i = 0; i < 2; i++) {            // 512 16B segs per operand
            int idx = i * 256 + tid;
            int row = idx >> 2, seg = idx & 3;
            uint32_t da = smem_u32(sA + row * (PITCH * 2) + seg * 16);
            const __half* srca = ag + (size_t)row * lda + seg * 8;
            asm volatile("cp.async.cg.shared.global [%0], [%1], 16;" :: "r"(da), "l"(srca));
            uint32_t db = smem_u32(sB + row * (PITCH * 2) + seg * 16);
            const __half* srcb = bg + (size_t)row * ldb + seg * 8;
            asm volatile("cp.async.cg.shared.global [%0], [%1], 16;" :: "r"(db), "l"(srcb));
        }
        asm volatile("cp.async.commit_group;" ::: "memory");
    };

    wmma::fragment<wmma::accumulator, 16, 16, 16, float> acc[2][4];
    #pragma unroll
    for (int mi = 0; mi < 2; mi++)
        #pragma unroll
        for (int ni = 0; ni < 4; ni++) {
            if (RES)
                wmma::load_matrix_sync(acc[mi][ni],
                    Rres + coff + (long long)(bm0 + wm + mi * 16) * ldc + (bn0 + wn + ni * 16),
                    ldc, wmma::mem_row_major);
            else
                wmma::fill_fragment(acc[mi][ni], 0.0f);
        }

    load_chunk(0);
    for (int kc = 0; kc < nk; kc++) {
        if (kc + 1 < nk) {
            load_chunk(kc + 1);
            asm volatile("cp.async.wait_group 1;" ::: "memory");
        } else {
            asm volatile("cp.async.wait_group 0;" ::: "memory");
        }
        __syncthreads();
        const __half* sA = (const __half*)(smem + (kc & 1) * STAGE_BYTES);
        const __half* sB = sA + BM * PITCH;
        #pragma unroll
        for (int kk = 0; kk < 2; kk++) {
            wmma::fragment<wmma::matrix_a, 16, 16, 16, __half, wmma::row_major> af[2];
            wmma::fragment<wmma::matrix_b, 16, 16, 16, __half, wmma::col_major> bf[4];
            #pragma unroll
            for (int mi = 0; mi < 2; mi++)
                wmma::load_matrix_sync(af[mi], sA + (wm + mi * 16) * PITCH + kk * 16, PITCH);
            #pragma unroll
            for (int ni = 0; ni < 4; ni++)
                wmma::load_matrix_sync(bf[ni], sB + (wn + ni * 16) * PITCH + kk * 16, PITCH);
            #pragma unroll
            for (int mi = 0; mi < 2; mi++)
                #pragma unroll
                for (int ni = 0; ni < 4; ni++)
                    wmma::mma_sync(acc[mi][ni], af[mi], bf[ni], acc[mi][ni]);
        }
        __syncthreads();
    }

    if (alpha != 1.0f) {
        #pragma unroll
        for (int mi = 0; mi < 2; mi++)
            #pragma unroll
            for (int ni = 0; ni < 4; ni++)
                #pragma unroll
                for (int e = 0; e < acc[mi][ni].num_elements; e++)
                    acc[mi][ni].x[e] *= alpha;
    }

    if (!HOUT) {
        float* Cp = C + coff;
        #pragma unroll
        for (int mi = 0; mi < 2; mi++)
            #pragma unroll
            for (int ni = 0; ni < 4; ni++)
                wmma::store_matrix_sync(
                    Cp + (long long)(bm0 + wm + mi * 16) * ldc + (bn0 + wn + ni * 16),
                    acc[mi][ni], ldc, wmma::mem_row_major);
    } else {
        float* stg = (float*)(smem + 2 * STAGE_BYTES + wid * 1024);
        #pragma unroll
        for (int mi = 0; mi < 2; mi++)
            #pragma unroll
            for (int ni = 0; ni < 4; ni++) {
                wmma::store_matrix_sync(stg, acc[mi][ni], 16, wmma::mem_row_major);
                __syncwarp();
                const int r  = lane >> 1;
                const int cb = (lane & 1) * 8;
                __half2 hv[4];
                #pragma unroll
                for (int j = 0; j < 4; j++)
                    hv[j] = __floats2half2_rn(stg[r * 16 + cb + 2 * j],
                                              stg[r * 16 + cb + 2 * j + 1]);
                const int grow = bm0 + wm + mi * 16 + r;
                const int gcol = wn + ni * 16 + cb;
                __half* dst;
                if (HSPLIT) {   // write straight into head-split [bh, t, d]
                    const int b = grow >> 11, t = grow & 2047;
                    dst = Ch + ((size_t)(b * NH + (bn0 >> 7)) * SEQ + t) * DH + gcol;
                } else {
                    dst = Ch + coff + (size_t)grow * ldc + bn0 + gcol;
                }
                *reinterpret_cast<uint4*>(dst) = *reinterpret_cast<uint4*>(hv);
                __syncwarp();
            }
    }
}

// ---------------- block reductions ----------------
__device__ __forceinline__ float blk_sum(float v) {
    __shared__ float sh_s[32];
    __shared__ float tot_s;
    int lane = threadIdx.x & 31, w = threadIdx.x >> 5;
    #pragma unroll
    for (int o = 16; o; o >>= 1) v += __shfl_xor_sync(0xffffffffu, v, o);
    if (lane == 0) sh_s[w] = v;
    __syncthreads();
    if (threadIdx.x == 0) {
        float r = 0.f; int nw = blockDim.x >> 5;
        for (int i = 0; i < nw; i++) r += sh_s[i];
        tot_s = r;
    }
    __syncthreads();
    float r = tot_s;
    __syncthreads();
    return r;
}
__device__ __forceinline__ float blk_max(float v) {
    __shared__ float sh_m[32];
    __shared__ float tot_m;
    int lane = threadIdx.x & 31, w = threadIdx.x >> 5;
    #pragma unroll
    for (int o = 16; o; o >>= 1) v = fmaxf(v, __shfl_xor_sync(0xffffffffu, v, o));
    if (lane == 0) sh_m[w] = v;
    __syncthreads();
    if (threadIdx.x == 0) {
        float r = -3.4e38f; int nw = blockDim.x >> 5;
        for (int i = 0; i < nw; i++) r = fmaxf(r, sh_m[i]);
        tot_m = r;
    }
    __syncthreads();
    float r = tot_m;
    __syncthreads();
    return r;
}

// ---------------- conversions / repack / softmax / norms ----------------
__global__ void f2h_k(const float* __restrict__ in, __half* __restrict__ out) {
    int i = (blockIdx.x * blockDim.x + threadIdx.x) * 4;
    float4 v = *reinterpret_cast<const float4*>(in + i);
    __half2 h[2];
    h[0] = __floats2half2_rn(v.x, v.y);
    h[1] = __floats2half2_rn(v.z, v.w);
    *reinterpret_cast<uint2*>(out + i) = *reinterpret_cast<uint2*>(h);
}

// v[b,s, d*16+h] -> vp[(b*16+h)*128 + d, s]  (head-dim-swap quirk)
__global__ void repack_v(const __half* __restrict__ src, __half* __restrict__ dst) {
    int idx = blockIdx.x * blockDim.x + threadIdx.x;
    int s = idx & 2047;
    int d = (idx >> 11) & 127;
    int bh = idx >> 18;
    int h = bh & 15, b = bh >> 4;
    dst[idx] = src[((size_t)(b * SEQ + s)) * EMB + d * NH + h];
}

__global__ void softmax_causal_k(const float* __restrict__ sc, __half* __restrict__ pr) {
    const int t  = blockIdx.x;
    const int bh = blockIdx.y;
    const float* row = sc + ((size_t)bh * SEQ + t) * SEQ;
    __half* orow = pr + ((size_t)bh * SEQ + t) * SEQ;
    __shared__ float buf[SEQ];
    const int n = t + 1;
    float mx = -3.4e38f;
    for (int i = threadIdx.x; i < n; i += blockDim.x) {
        float v = row[i]; buf[i] = v; mx = fmaxf(mx, v);
    }
    mx = blk_max(mx);
    float sum = 0.f;
    for (int i = threadIdx.x; i < n; i += blockDim.x) {
        float e = __expf(buf[i] - mx); buf[i] = e; sum += e;
    }
    sum = blk_sum(sum);
    const float inv = 1.0f / sum;
    for (int i = threadIdx.x; i < n; i += blockDim.x)
        orow[i] = __float2half_rn(buf[i] * inv);
    for (int i = n + threadIdx.x; i < SEQ; i += blockDim.x)
        orow[i] = __float2half_rn(0.0f);
}

__global__ void layernorm_h(const float* __restrict__ in, __half* __restrict__ out,
                            const float* __restrict__ g, const float* __restrict__ b) {
    const float* row = in + (size_t)blockIdx.x * EMB;
    __half* orow = out + (size_t)blockIdx.x * EMB;
    __shared__ float buf[EMB];
    float s = 0.f;
    for (int i = threadIdx.x; i < EMB; i += blockDim.x) { float v = row[i]; buf[i] = v; s += v; }
    const float mu = blk_sum(s) * (1.0f / EMB);
    float sq = 0.f;
    for (int i = threadIdx.x; i < EMB; i += blockDim.x) { float d = buf[i] - mu; sq += d * d; }
    const float var = blk_sum(sq) * (1.0f / EMB);
    const float inv = rsqrtf(var + 1e-5f);
    for (int i = threadIdx.x; i < EMB; i += blockDim.x)
        orow[i] = __float2half_rn((buf[i] - mu) * inv * g[i] + b[i]);
}

// x := rmsnorm(x) (fp32, residual base) and xh := half(x)
__global__ void rmsnorm_dual(float* __restrict__ x, __half* __restrict__ xh,
                             const float* __restrict__ g) {
    float* row = x + (size_t)blockIdx.x * EMB;
    __half* orow = xh + (size_t)blockIdx.x * EMB;
    __shared__ float buf[EMB];
    float ss = 0.f;
    for (int i = threadIdx.x; i < EMB; i += blockDim.x) { float v = row[i]; buf[i] = v; ss += v * v; }
    ss = blk_sum(ss);
    const float sc = rsqrtf(ss * (1.0f / EMB) + 1e-6f);
    for (int i = threadIdx.x; i < EMB; i += blockDim.x) {
        float r = g[i] * buf[i] * sc;
        row[i] = r;
        orow[i] = __float2half_rn(r);
    }
}

__global__ void swiglu_k(float* __restrict__ w, const float* __restrict__ u,
                         const float* __restrict__ beta) {
    const float b = beta[0];
    const int total = MTOT * EMB;
    for (int i = blockIdx.x * blockDim.x + threadIdx.x; i < total;
         i += gridDim.x * blockDim.x) {
        float wv = w[i];
        float s = 1.0f / (1.0f + __expf(-b * wv));
        w[i] = wv * s * u[i];
    }
}

__global__ void final_k(const float* __restrict__ x2, const float* __restrict__ gg,
                        const float* __restrict__ gamma, float* __restrict__ out) {
    const size_t r = blockIdx.x;
    const float* grow = gg + r * EMB;
    __shared__ float buf[EMB];
    float ss = 0.f;
    for (int i = threadIdx.x; i < EMB; i += blockDim.x) { float v = grow[i]; buf[i] = v; ss += v * v; }
    ss = blk_sum(ss);
    const float sc = rsqrtf(ss * (1.0f / EMB) + 1e-6f);
    for (int i = threadIdx.x; i < EMB; i += blockDim.x)
        out[r * EMB + i] = x2[r * EMB + i] + gamma[i] * buf[i] * sc;
}

// ---------------- launcher ----------------
extern "C" void kernel_launch(void* const* d_in, const int* in_sizes, int n_in,
                              void* d_out, int out_size) {
    const float* x     = (const float*)d_in[0];
    const float* Wq    = (const float*)d_in[1];
    const float* Wk    = (const float*)d_in[2];
    const float* Wv    = (const float*)d_in[3];
    const float* Wo    = (const float*)d_in[4];
    const float* ln_g  = (const float*)d_in[5];
    const float* ln_b  = (const float*)d_in[6];
    const float* rms_g = (const float*)d_in[7];
    const float* W0    = (const float*)d_in[8];
    const float* swW   = (const float*)d_in[9];
    const float* swV   = (const float*)d_in[10];
    const float* swb   = (const float*)d_in[11];
    const float* mrg   = (const float*)d_in[12];
    float* out = (float*)d_out;

    __half *xh, *wh, *qh, *kh, *v, *vp, *pr, *cth, *x2h, *hh;
    float *sc, *ctx, *xa, *w, *u;
    cudaGetSymbolAddress((void**)&xh,  g_xh);
    cudaGetSymbolAddress((void**)&wh,  g_wh);
    cudaGetSymbolAddress((void**)&qh,  g_qh);
    cudaGetSymbolAddress((void**)&kh,  g_kh);
    cudaGetSymbolAddress((void**)&v,   g_v);
    cudaGetSymbolAddress((void**)&vp,  g_vp);
    cudaGetSymbolAddress((void**)&sc,  g_sc);
    cudaGetSymbolAddress((void**)&pr,  g_pr);
    cudaGetSymbolAddress((void**)&ctx, g_ctx);
    cudaGetSymbolAddress((void**)&cth, g_cth);
    cudaGetSymbolAddress((void**)&xa,  g_xa);
    cudaGetSymbolAddress((void**)&x2h, g_x2h);
    cudaGetSymbolAddress((void**)&hh,  g_hh);
    cudaGetSymbolAddress((void**)&w,   g_w);
    cudaGetSymbolAddress((void**)&u,   g_u);

    __half* wqh = wh + 0ll * EMB * EMB;
    __half* wkh = wh + 1ll * EMB * EMB;
    __half* wvh = wh + 2ll * EMB * EMB;
    __half* woh = wh + 3ll * EMB * EMB;
    __half* w0h = wh + 4ll * EMB * EMB;
    __half* wwh = wh + 5ll * EMB * EMB;
    __half* wvh2= wh + 6ll * EMB * EMB;

    const float scale = 0.08838834764831845f;  // 1/sqrt(128)
    const int NEW = MTOT * EMB;                // 8,388,608
    const int NW  = EMB * EMB;                 // 4,194,304
    dim3 blk(256);

    // fp32 -> fp16 operand conversions
    f2h_k<<<NEW / 1024, 256>>>(x,   xh);
    f2h_k<<<NW  / 1024, 256>>>(Wq,  wqh);
    f2h_k<<<NW  / 1024, 256>>>(Wk,  wkh);
    f2h_k<<<NW  / 1024, 256>>>(Wv,  wvh);
    f2h_k<<<NW  / 1024, 256>>>(Wo,  woh);
    f2h_k<<<NW  / 1024, 256>>>(W0,  w0h);
    f2h_k<<<NW  / 1024, 256>>>(swW, wwh);
    f2h_k<<<NW  / 1024, 256>>>(swV, wvh2);

    dim3 gp(EMB / BN, MTOT / BM, 1);           // (16,32,1)

    // q,k projections with fused head-split repack; v plain
    gemm_h<true, true, false,false,false><<<gp, blk, SMEM_GEMM>>>(64, xh, EMB, 0, wqh, EMB, 0, nullptr, qh, DH, nullptr, 1.0f,  1, 0, 0);
    gemm_h<true, true, false,false,false><<<gp, blk, SMEM_GEMM>>>(64, xh, EMB, 0, wkh, EMB, 0, nullptr, kh, DH, nullptr, scale, 1, 0, 0);
    gemm_h<true, false,false,false,false><<<gp, blk, SMEM_GEMM>>>(64, xh, EMB, 0, wvh, EMB, 0, nullptr, v,  EMB, nullptr, 1.0f,  1, 0, 0);

    repack_v<<<NEW / 256, 256>>>(v, vp);

    // scores = Qh @ Kh^T (batched per bh, skip blocks above diagonal)
    dim3 gs(SEQ / BN, SEQ / BM, NB * NH);      // (16,16,32)
    gemm_h<false,false,false,true, false><<<gs, blk, SMEM_GEMM>>>(4,
        qh, DH, SEQ, kh, DH, SEQ, sc, nullptr, SEQ, nullptr, 1.0f,
        1, (long long)SEQ * SEQ, 0);

    softmax_causal_k<<<dim3(SEQ, NB * NH), 256>>>(sc, pr);

    // ctx = P @ Vp^T (NT), causal k-cap, packed [b,t,h*Dh+d] fp32 output
    dim3 gpv(1, SEQ / BM, NB * NH);
    gemm_h<false,false,false,false,true ><<<gpv, blk, SMEM_GEMM>>>(64,
        pr, SEQ, SEQ, vp, SEQ, DH, ctx, nullptr, EMB, nullptr, 1.0f,
        NH, (long long)SEQ * EMB, (long long)DH);

    layernorm_h<<<MTOT, 256>>>(ctx, cth, ln_g, ln_b);

    // xa = x + cth @ Wo^T (fp32, residual fused via accumulator init)
    gemm_h<false,false,true, false,false><<<gp, blk, SMEM_GEMM>>>(64, cth, EMB, 0, woh, EMB, 0, xa, nullptr, EMB, x, 1.0f, 1, 0, 0);

    rmsnorm_dual<<<MTOT, 256>>>(xa, x2h, rms_g);

    gemm_h<true, false,false,false,false><<<gp, blk, SMEM_GEMM>>>(64, x2h, EMB, 0, w0h, EMB, 0, nullptr, hh, EMB, nullptr, 1.0f, 1, 0, 0);
    gemm_h<false,false,false,false,false><<<gp, blk, SMEM_GEMM>>>(64, hh,  EMB, 0, wwh, EMB, 0, w, nullptr, EMB, nullptr, 1.0f, 1, 0, 0);
    gemm_h<false,false,false,false,false><<<gp, blk, SMEM_GEMM>>>(64, hh,  EMB, 0, wvh2,EMB, 0, u, nullptr, EMB, nullptr, 1.0f, 1, 0, 0);

    swiglu_k<<<4096, 256>>>(w, u, swb);
    final_k<<<MTOT, 256>>>(xa, w, mrg, out);
}

// round 4
// speedup vs baseline: 3.4548x; 1.1135x over previous
#include <cuda_runtime.h>
#include <cuda_fp16.h>
#include <mma.h>
#include <cstdint>

using namespace nvcuda;

#define SEQ 2048
#define EMB 2048
#define NB  2
#define NH  16
#define DH  128
#define MTOT (NB*SEQ)   // 4096
#define PLANE ((size_t)MTOT*EMB)

// ---------------- scratch (static device globals) ----------------
__device__ __half g_xh  [MTOT*EMB];
__device__ __half g_wh  [7][EMB*EMB];       // wq,wk,wv,wo,w0,sww,swv (contiguous)
__device__ __half g_qkvh[3][MTOT*EMB];      // plane0: qh [bh,t,d]; 1: kh [bh,s,d]; 2: v [b,s,E]
__device__ __half g_vp  [MTOT*EMB];         // [bh, d, s]
__device__ float  g_sc  [NB*NH*SEQ*SEQ];    // scores fp32 (512MB)
__device__ __half g_pr  [NB*NH*SEQ*SEQ];    // probs half
__device__ float  g_ctx [MTOT*EMB];
__device__ __half g_cth [MTOT*EMB];
__device__ float  g_xa  [MTOT*EMB];
__device__ __half g_x2h [MTOT*EMB];
__device__ __half g_hh  [MTOT*EMB];
__device__ float  g_wu  [2][MTOT*EMB];      // plane0: w, plane1: u

__device__ __forceinline__ uint32_t smem_u32(const void* p) {
    uint32_t a;
    asm("{ .reg .u64 t; cvta.to.shared.u64 t, %1; cvt.u32.u64 %0, t; }" : "=r"(a) : "l"(p));
    return a;
}

// ---------------- fp16 wmma NT GEMM, 3-stage cp.async ----------------
// C[128,128] tile = A[128,K] @ B[128,K]^T ; K in chunks of 32 halves.
constexpr int BM = 128, BN = 128, PITCH = 40;          // pitch in halves
constexpr int STG_BYTES   = BM * PITCH * 2;            // 10240 per operand
constexpr int STAGE_BYTES = 2 * STG_BYTES;             // 20480 (A+B)
constexpr int NSTG = 3;
constexpr int SMEM_GEMM   = NSTG * STAGE_BYTES;        // 61440

// OMODE: 0 = fp32 out (opt RES); 1 = half plain out; 2 = QKV combined (3 planes)
template<int OMODE, bool RES, bool CSKIP, bool KCAP>
__global__ void __launch_bounds__(256, 2)
gemm_h(int nk,
       const __half* __restrict__ A, int lda, int zRowA,
       const __half* __restrict__ B, int ldb, int zRowB,
       float* __restrict__ C, __half* __restrict__ Ch, int ldc,
       const float* __restrict__ Rres, float alphaA, float alphaB, int zdiv,
       long long sC1, long long sC2)
{
    const int bn0 = blockIdx.x * BN;
    const int bm0 = blockIdx.y * BM;
    if (CSKIP && bn0 > bm0 + BM - 1) return;     // fully above causal diagonal
    const int z = blockIdx.z;
    if (KCAP) nk = min(nk, (bm0 >> 5) + 4);      // causal k-cap (32-key chunks)

    extern __shared__ __align__(128) char smem[];
    const int tid  = threadIdx.x;
    const int wid  = tid >> 5;
    const int lane = tid & 31;
    const int wm = (wid & 3) * 32;
    const int wn = (wid >> 2) * 64;

    const __half* Abase = A + (size_t)(z * zRowA + bm0) * lda;
    const __half* Bbase = B + (size_t)(z * zRowB + bn0) * ldb;
    const long long coff = (long long)(z / zdiv) * sC1 + (long long)(z % zdiv) * sC2;

    auto load_chunk = [&](int kc) {
        const int st = kc % NSTG;
        char* sA = smem + st * STAGE_BYTES;
        char* sB = sA + STG_BYTES;
        const __half* ag = Abase + kc * 32;
        const __half* bg = Bbase + kc * 32;
        #pragma unroll
        for (int i = 0; i < 2; i++) {            // 512 16B segs per operand
            int idx = i * 256 + tid;
            int row = idx >> 2, seg = idx & 3;
            uint32_t da = smem_u32(sA + row * (PITCH * 2) + seg * 16);
            const __half* srca = ag + (size_t)row * lda + seg * 8;
            asm volatile("cp.async.cg.shared.global [%0], [%1], 16;" :: "r"(da), "l"(srca));
            uint32_t db = smem_u32(sB + row * (PITCH * 2) + seg * 16);
            const __half* srcb = bg + (size_t)row * ldb + seg * 8;
            asm volatile("cp.async.cg.shared.global [%0], [%1], 16;" :: "r"(db), "l"(srcb));
        }
        asm volatile("cp.async.commit_group;" ::: "memory");
    };

    wmma::fragment<wmma::accumulator, 16, 16, 16, float> acc[2][4];
    #pragma unroll
    for (int mi = 0; mi < 2; mi++)
        #pragma unroll
        for (int ni = 0; ni < 4; ni++) {
            if (RES)
                wmma::load_matrix_sync(acc[mi][ni],
                    Rres + coff + (long long)(bm0 + wm + mi * 16) * ldc + (bn0 + wn + ni * 16),
                    ldc, wmma::mem_row_major);
            else
                wmma::fill_fragment(acc[mi][ni], 0.0f);
        }

    load_chunk(0);
    if (nk > 1) load_chunk(1);

    for (int kc = 0; kc < nk; kc++) {
        if (kc + 1 < nk)
            asm volatile("cp.async.wait_group 1;" ::: "memory");
        else
            asm volatile("cp.async.wait_group 0;" ::: "memory");
        __syncthreads();
        if (kc + 2 < nk) load_chunk(kc + 2);

        const __half* sA = (const __half*)(smem + (kc % NSTG) * STAGE_BYTES);
        const __half* sB = sA + BM * PITCH;
        #pragma unroll
        for (int kk = 0; kk < 2; kk++) {
            wmma::fragment<wmma::matrix_a, 16, 16, 16, __half, wmma::row_major> af[2];
            #pragma unroll
            for (int mi = 0; mi < 2; mi++)
                wmma::load_matrix_sync(af[mi], sA + (wm + mi * 16) * PITCH + kk * 16, PITCH);
            #pragma unroll
            for (int nh = 0; nh < 2; nh++) {     // bf live-range kept small (reg pressure)
                wmma::fragment<wmma::matrix_b, 16, 16, 16, __half, wmma::col_major> bf[2];
                #pragma unroll
                for (int j = 0; j < 2; j++)
                    wmma::load_matrix_sync(bf[j], sB + (wn + (nh * 2 + j) * 16) * PITCH + kk * 16, PITCH);
                #pragma unroll
                for (int mi = 0; mi < 2; mi++)
                    #pragma unroll
                    for (int j = 0; j < 2; j++)
                        wmma::mma_sync(acc[mi][nh * 2 + j], af[mi], bf[j], acc[mi][nh * 2 + j]);
            }
        }
    }

    const float alpha = (OMODE == 2) ? ((z == 1) ? alphaB : alphaA) : alphaA;
    if (alpha != 1.0f) {
        #pragma unroll
        for (int mi = 0; mi < 2; mi++)
            #pragma unroll
            for (int ni = 0; ni < 4; ni++)
                #pragma unroll
                for (int e = 0; e < acc[mi][ni].num_elements; e++)
                    acc[mi][ni].x[e] *= alpha;
    }

    if (OMODE == 0) {
        float* Cp = C + coff;
        #pragma unroll
        for (int mi = 0; mi < 2; mi++)
            #pragma unroll
            for (int ni = 0; ni < 4; ni++)
                wmma::store_matrix_sync(
                    Cp + (long long)(bm0 + wm + mi * 16) * ldc + (bn0 + wn + ni * 16),
                    acc[mi][ni], ldc, wmma::mem_row_major);
    } else {
        __syncthreads();                          // mainloop buffers now reusable as staging
        float* stg = (float*)smem + wid * 256;
        __half* Cp = (OMODE == 2) ? (Ch + (size_t)z * PLANE) : Ch;
        const bool hsplit = (OMODE == 2) && (z < 2);
        #pragma unroll
        for (int mi = 0; mi < 2; mi++)
            #pragma unroll
            for (int ni = 0; ni < 4; ni++) {
                wmma::store_matrix_sync(stg, acc[mi][ni], 16, wmma::mem_row_major);
                __syncwarp();
                const int r  = lane >> 1;
                const int cb = (lane & 1) * 8;
                __half2 hv[4];
                #pragma unroll
                for (int j = 0; j < 4; j++)
                    hv[j] = __floats2half2_rn(stg[r * 16 + cb + 2 * j],
                                              stg[r * 16 + cb + 2 * j + 1]);
                const int grow = bm0 + wm + mi * 16 + r;
                const int gcol = wn + ni * 16 + cb;
                __half* dst;
                if (hsplit) {                      // write into head-split [bh, t, d]
                    const int b = grow >> 11, t = grow & 2047;
                    dst = Cp + ((size_t)((b << 4) + (bn0 >> 7)) * SEQ + t) * DH + gcol;
                } else {
                    dst = Cp + coff + (size_t)grow * ldc + bn0 + gcol;
                }
                *reinterpret_cast<uint4*>(dst) = *reinterpret_cast<uint4*>(hv);
                __syncwarp();
            }
    }
}

// ---------------- block reductions ----------------
__device__ __forceinline__ float blk_sum(float v) {
    __shared__ float sh_s[32];
    __shared__ float tot_s;
    int lane = threadIdx.x & 31, w = threadIdx.x >> 5;
    #pragma unroll
    for (int o = 16; o; o >>= 1) v += __shfl_xor_sync(0xffffffffu, v, o);
    if (lane == 0) sh_s[w] = v;
    __syncthreads();
    if (threadIdx.x == 0) {
        float r = 0.f; int nw = blockDim.x >> 5;
        for (int i = 0; i < nw; i++) r += sh_s[i];
        tot_s = r;
    }
    __syncthreads();
    float r = tot_s;
    __syncthreads();
    return r;
}
__device__ __forceinline__ float blk_max(float v) {
    __shared__ float sh_m[32];
    __shared__ float tot_m;
    int lane = threadIdx.x & 31, w = threadIdx.x >> 5;
    #pragma unroll
    for (int o = 16; o; o >>= 1) v = fmaxf(v, __shfl_xor_sync(0xffffffffu, v, o));
    if (lane == 0) sh_m[w] = v;
    __syncthreads();
    if (threadIdx.x == 0) {
        float r = -3.4e38f; int nw = blockDim.x >> 5;
        for (int i = 0; i < nw; i++) r = fmaxf(r, sh_m[i]);
        tot_m = r;
    }
    __syncthreads();
    float r = tot_m;
    __syncthreads();
    return r;
}

// ---------------- conversions / repack / softmax / norms ----------------
__global__ void f2h_k(const float* __restrict__ in, __half* __restrict__ out) {
    int i = (blockIdx.x * blockDim.x + threadIdx.x) * 4;
    float4 v = *reinterpret_cast<const float4*>(in + i);
    __half2 h[2];
    h[0] = __floats2half2_rn(v.x, v.y);
    h[1] = __floats2half2_rn(v.z, v.w);
    *reinterpret_cast<uint2*>(out + i) = *reinterpret_cast<uint2*>(h);
}

// v[b,s, d*16+h] -> vp[(b*16+h)*128 + d, s]  (head-dim-swap quirk)
__global__ void repack_v(const __half* __restrict__ src, __half* __restrict__ dst) {
    int idx = blockIdx.x * blockDim.x + threadIdx.x;
    int s = idx & 2047;
    int d = (idx >> 11) & 127;
    int bh = idx >> 18;
    int h = bh & 15, b = bh >> 4;
    dst[idx] = src[((size_t)(b * SEQ + s)) * EMB + d * NH + h];
}

__global__ void softmax_causal_k(const float* __restrict__ sc, __half* __restrict__ pr) {
    const int t  = blockIdx.x;
    const int bh = blockIdx.y;
    const float* row = sc + ((size_t)bh * SEQ + t) * SEQ;
    __half* orow = pr + ((size_t)bh * SEQ + t) * SEQ;
    __shared__ float buf[SEQ];
    const int n = t + 1;
    float mx = -3.4e38f;
    for (int i = threadIdx.x; i < n; i += blockDim.x) {
        float v = row[i]; buf[i] = v; mx = fmaxf(mx, v);
    }
    mx = blk_max(mx);
    float sum = 0.f;
    for (int i = threadIdx.x; i < n; i += blockDim.x) {
        float e = __expf(buf[i] - mx); buf[i] = e; sum += e;
    }
    sum = blk_sum(sum);
    const float inv = 1.0f / sum;
    for (int i = threadIdx.x; i < n; i += blockDim.x)
        orow[i] = __float2half_rn(buf[i] * inv);
    // PV's causal k-cap only ever reads up to the end of this 128-row block
    const int fend = ((t >> 7) + 1) << 7;
    for (int i = n + threadIdx.x; i < fend; i += blockDim.x)
        orow[i] = __float2half_rn(0.0f);
}

__global__ void layernorm_h(const float* __restrict__ in, __half* __restrict__ out,
                            const float* __restrict__ g, const float* __restrict__ b) {
    const float* row = in + (size_t)blockIdx.x * EMB;
    __half* orow = out + (size_t)blockIdx.x * EMB;
    __shared__ float buf[EMB];
    float s = 0.f;
    for (int i = threadIdx.x; i < EMB; i += blockDim.x) { float v = row[i]; buf[i] = v; s += v; }
    const float mu = blk_sum(s) * (1.0f / EMB);
    float sq = 0.f;
    for (int i = threadIdx.x; i < EMB; i += blockDim.x) { float d = buf[i] - mu; sq += d * d; }
    const float var = blk_sum(sq) * (1.0f / EMB);
    const float inv = rsqrtf(var + 1e-5f);
    for (int i = threadIdx.x; i < EMB; i += blockDim.x)
        orow[i] = __float2half_rn((buf[i] - mu) * inv * g[i] + b[i]);
}

// x := rmsnorm(x) (fp32, residual base) and xh := half(x)
__global__ void rmsnorm_dual(float* __restrict__ x, __half* __restrict__ xh,
                             const float* __restrict__ g) {
    float* row = x + (size_t)blockIdx.x * EMB;
    __half* orow = xh + (size_t)blockIdx.x * EMB;
    __shared__ float buf[EMB];
    float ss = 0.f;
    for (int i = threadIdx.x; i < EMB; i += blockDim.x) { float v = row[i]; buf[i] = v; ss += v * v; }
    ss = blk_sum(ss);
    const float sc = rsqrtf(ss * (1.0f / EMB) + 1e-6f);
    for (int i = threadIdx.x; i < EMB; i += blockDim.x) {
        float r = g[i] * buf[i] * sc;
        row[i] = r;
        orow[i] = __float2half_rn(r);
    }
}

// out = x2 + mlp_rms_g * g * rsqrt(mean(g^2)+eps),  g = w*sigmoid(beta*w)*u  (swiglu fused)
__global__ void final_k(const float* __restrict__ x2, const float* __restrict__ wv,
                        const float* __restrict__ uv, const float* __restrict__ beta,
                        const float* __restrict__ gamma, float* __restrict__ out) {
    const size_t r = blockIdx.x;
    const float bet = beta[0];
    const float* wrow = wv + r * EMB;
    const float* urow = uv + r * EMB;
    __shared__ float buf[EMB];
    float ss = 0.f;
    for (int i = threadIdx.x; i < EMB; i += blockDim.x) {
        float wq = wrow[i];
        float s = 1.0f / (1.0f + __expf(-bet * wq));
        float gq = wq * s * urow[i];
        buf[i] = gq; ss += gq * gq;
    }
    ss = blk_sum(ss);
    const float sc = rsqrtf(ss * (1.0f / EMB) + 1e-6f);
    for (int i = threadIdx.x; i < EMB; i += blockDim.x)
        out[r * EMB + i] = x2[r * EMB + i] + gamma[i] * buf[i] * sc;
}

// ---------------- launcher ----------------
extern "C" void kernel_launch(void* const* d_in, const int* in_sizes, int n_in,
                              void* d_out, int out_size) {
    const float* x     = (const float*)d_in[0];
    const float* Wq    = (const float*)d_in[1];
    const float* Wk    = (const float*)d_in[2];
    const float* Wv    = (const float*)d_in[3];
    const float* Wo    = (const float*)d_in[4];
    const float* ln_g  = (const float*)d_in[5];
    const float* ln_b  = (const float*)d_in[6];
    const float* rms_g = (const float*)d_in[7];
    const float* W0    = (const float*)d_in[8];
    const float* swW   = (const float*)d_in[9];
    const float* swV   = (const float*)d_in[10];
    const float* swb   = (const float*)d_in[11];
    const float* mrg   = (const float*)d_in[12];
    float* out = (float*)d_out;

    __half *xh, *wh, *qkv, *vp, *pr, *cth, *x2h, *hh;
    float *sc, *ctx, *xa, *wu;
    cudaGetSymbolAddress((void**)&xh,  g_xh);
    cudaGetSymbolAddress((void**)&wh,  g_wh);
    cudaGetSymbolAddress((void**)&qkv, g_qkvh);
    cudaGetSymbolAddress((void**)&vp,  g_vp);
    cudaGetSymbolAddress((void**)&sc,  g_sc);
    cudaGetSymbolAddress((void**)&pr,  g_pr);
    cudaGetSymbolAddress((void**)&ctx, g_ctx);
    cudaGetSymbolAddress((void**)&cth, g_cth);
    cudaGetSymbolAddress((void**)&xa,  g_xa);
    cudaGetSymbolAddress((void**)&x2h, g_x2h);
    cudaGetSymbolAddress((void**)&hh,  g_hh);
    cudaGetSymbolAddress((void**)&wu,  g_wu);

    __half* qh = qkv + 0 * PLANE;
    __half* kh = qkv + 1 * PLANE;
    __half* v  = qkv + 2 * PLANE;
    float*  wv = wu + 0 * PLANE;
    float*  uv = wu + 1 * PLANE;
    const long long NW = (long long)EMB * EMB;

    cudaFuncSetAttribute(gemm_h<2,false,false,false>, cudaFuncAttributeMaxDynamicSharedMemorySize, SMEM_GEMM);
    cudaFuncSetAttribute(gemm_h<0,false,true ,false>, cudaFuncAttributeMaxDynamicSharedMemorySize, SMEM_GEMM);
    cudaFuncSetAttribute(gemm_h<0,false,false,true >, cudaFuncAttributeMaxDynamicSharedMemorySize, SMEM_GEMM);
    cudaFuncSetAttribute(gemm_h<0,true ,false,false>, cudaFuncAttributeMaxDynamicSharedMemorySize, SMEM_GEMM);
    cudaFuncSetAttribute(gemm_h<1,false,false,false>, cudaFuncAttributeMaxDynamicSharedMemorySize, SMEM_GEMM);
    cudaFuncSetAttribute(gemm_h<0,false,false,false>, cudaFuncAttributeMaxDynamicSharedMemorySize, SMEM_GEMM);

    const float scale = 0.08838834764831845f;  // 1/sqrt(128)
    const int NEW = MTOT * EMB;                // 8,388,608
    dim3 blk(256);

    // fp32 -> fp16 operand conversions (weights land contiguously in g_wh)
    f2h_k<<<NEW / 1024, 256>>>(x,   xh);
    f2h_k<<<NW  / 1024, 256>>>(Wq,  wh + 0 * NW);
    f2h_k<<<NW  / 1024, 256>>>(Wk,  wh + 1 * NW);
    f2h_k<<<NW  / 1024, 256>>>(Wv,  wh + 2 * NW);
    f2h_k<<<NW  / 1024, 256>>>(Wo,  wh + 3 * NW);
    f2h_k<<<NW  / 1024, 256>>>(W0,  wh + 4 * NW);
    f2h_k<<<NW  / 1024, 256>>>(swW, wh + 5 * NW);
    f2h_k<<<NW  / 1024, 256>>>(swV, wh + 6 * NW);

    // merged QKV projection: z selects weight plane + output plane
    dim3 gqkv(EMB / BN, MTOT / BM, 3);         // (16,32,3)
    gemm_h<2,false,false,false><<<gqkv, blk, SMEM_GEMM>>>(64,
        xh, EMB, 0, wh, EMB, EMB, nullptr, qkv, EMB, nullptr, 1.0f, scale, 1, 0, 0);

    repack_v<<<NEW / 256, 256>>>(v, vp);

    // scores = Qh @ Kh^T (batched per bh, skip blocks above diagonal)
    dim3 gs(SEQ / BN, SEQ / BM, NB * NH);      // (16,16,32)
    gemm_h<0,false,true,false><<<gs, blk, SMEM_GEMM>>>(4,
        qh, DH, SEQ, kh, DH, SEQ, sc, nullptr, SEQ, nullptr, 1.0f, 1.0f,
        1, (long long)SEQ * SEQ, 0);

    softmax_causal_k<<<dim3(SEQ, NB * NH), 256>>>(sc, pr);

    // ctx = P @ Vp^T (NT), causal k-cap, packed [b,t,h*Dh+d] fp32 output
    dim3 gpv(1, SEQ / BM, NB * NH);
    gemm_h<0,false,false,true><<<gpv, blk, SMEM_GEMM>>>(64,
        pr, SEQ, SEQ, vp, SEQ, DH, ctx, nullptr, EMB, nullptr, 1.0f, 1.0f,
        NH, (long long)SEQ * EMB, (long long)DH);

    layernorm_h<<<MTOT, 256>>>(ctx, cth, ln_g, ln_b);

    // xa = x + cth @ Wo^T (fp32, residual fused via accumulator init)
    dim3 gp(EMB / BN, MTOT / BM, 1);           // (16,32,1)
    gemm_h<0,true,false,false><<<gp, blk, SMEM_GEMM>>>(64,
        cth, EMB, 0, wh + 3 * NW, EMB, 0, xa, nullptr, EMB, x, 1.0f, 1.0f, 1, 0, 0);

    rmsnorm_dual<<<MTOT, 256>>>(xa, x2h, rms_g);

    // h = x2 @ W0^T (half out)
    gemm_h<1,false,false,false><<<gp, blk, SMEM_GEMM>>>(64,
        x2h, EMB, 0, wh + 4 * NW, EMB, 0, nullptr, hh, EMB, nullptr, 1.0f, 1.0f, 1, 0, 0);

    // merged swW/swV: z selects weight plane (contiguous) + fp32 output plane
    dim3 gsw(EMB / BN, MTOT / BM, 2);          // (16,32,2)
    gemm_h<0,false,false,false><<<gsw, blk, SMEM_GEMM>>>(64,
        hh, EMB, 0, wh + 5 * NW, EMB, EMB, wu, nullptr, EMB, nullptr, 1.0f, 1.0f,
        1, (long long)PLANE, 0);

    final_k<<<MTOT, 256>>>(xa, wv, uv, swb, mrg, out);   // swiglu + rmsnorm + residual
}